// round 2
// baseline (speedup 1.0000x reference)
#include <cuda_runtime.h>
#include <cfloat>

// ---------------- static scratch (no allocations allowed) ----------------
#define MAX_NF   15200000   // >= N_cur * F = 50000*300
#define MAX_NODE 50048
#define MAX_F    304

__device__ float g_nodebuf[MAX_NF];   // per-(node,feat) running max (or min) of z
__device__ float g_outpre[MAX_NF];    // ReLU(agg@W2+b2) before BN2
__device__ int   g_flags[MAX_NODE];   // node has >=1 edge
__device__ float g_sums[MAX_F],  g_sumsq[MAX_F];   // BN1 stats
__device__ float g_sums2[MAX_F], g_sumsq2[MAX_F];  // BN2 stats
__device__ float g_scale1[MAX_F], g_shift1[MAX_F];
__device__ float g_scale2[MAX_F], g_shift2[MAX_F];

#define BE 128
#define BF 128
#define BK 16
#define NT 256

// ---------------- init: nodebuf per sign(g1), flags, stat accumulators ----------------
__global__ void k_init(const float* __restrict__ g1, int NCur, int F) {
    int total = NCur * F;
    int tid = blockIdx.x * blockDim.x + threadIdx.x;
    for (int idx = tid; idx < total; idx += gridDim.x * blockDim.x) {
        int f = idx % F;
        g_nodebuf[idx] = (g1[f] >= 0.f) ? 0.f : FLT_MAX;  // z >= 0 always (post-ReLU)
    }
    if (tid < NCur) g_flags[tid] = 0;
    if (tid < F) { g_sums[tid]=0.f; g_sumsq[tid]=0.f; g_sums2[tid]=0.f; g_sumsq2[tid]=0.f; }
}

__global__ void k_flag(const int* __restrict__ cur_idx, int E) {
    int e = blockIdx.x * blockDim.x + threadIdx.x;
    if (e < E) g_flags[cur_idx[e]] = 1;   // benign race, same value
}

// ---------------- fused edge pipeline: gather -> GEMM -> ReLU -> stats + scatter max/min ----------------
__global__ __launch_bounds__(NT, 2)
void k_edge(const float* __restrict__ lastF, const float* __restrict__ lastC,
            const float* __restrict__ curC,
            const int* __restrict__ cur_idx, const int* __restrict__ last_idx,
            const float* __restrict__ W1, const float* __restrict__ b1,
            const float* __restrict__ g1,
            int E, int F, int NCur)
{
    const int Din = F + 3;
    __shared__ float As[BK][BE];
    __shared__ float Bs[BK][BF + 4];
    __shared__ int   sL[BE], sC[BE];
    __shared__ float sSum[BF], sSq[BF];

    const int t  = threadIdx.x;
    const int e0 = blockIdx.x * BE;
    const int f0 = blockIdx.y * BF;

    for (int i = t; i < BE; i += NT) {
        int e = e0 + i;
        sL[i] = (e < E) ? last_idx[e] : 0;
        sC[i] = (e < E) ? cur_idx[e]  : 0;
    }
    for (int i = t; i < BF; i += NT) { sSum[i] = 0.f; sSq[i] = 0.f; }
    __syncthreads();

    float acc[8][8];
#pragma unroll
    for (int i = 0; i < 8; ++i)
#pragma unroll
        for (int j = 0; j < 8; ++j) acc[i][j] = 0.f;

    const int tx = t & 15;     // feature group
    const int ty = t >> 4;     // edge group

    const int nTiles = (Din + BK - 1) / BK;
    for (int kt0 = 0; kt0 < nTiles; ++kt0) {
        const int kt = kt0 * BK;
        // ---- A tile: gathered edge features, stored k-major ----
        if (kt + BK <= F) {                 // pure-feature tile, vector path
#pragma unroll
            for (int it = 0; it < 2; ++it) {
                int slot = it * NT + t;
                int i  = slot & (BE - 1);
                int kg = slot >> 7;         // 0..3
                const float4 v = *reinterpret_cast<const float4*>(
                    &lastF[(size_t)sL[i] * F + kt + kg * 4]);
                As[kg*4+0][i] = v.x; As[kg*4+1][i] = v.y;
                As[kg*4+2][i] = v.z; As[kg*4+3][i] = v.w;
            }
        } else {                            // boundary tile (features + coord deltas)
            for (int slot = t; slot < BE * BK; slot += NT) {
                int i  = slot & (BE - 1);
                int kk = slot >> 7;
                int k  = kt + kk;
                float v = 0.f;
                if (k < F)        v = lastF[(size_t)sL[i] * F + k];
                else if (k < Din) v = lastC[sL[i]*3 + (k - F)] - curC[sC[i]*3 + (k - F)];
                As[kk][i] = v;
            }
        }
        // ---- B tile: W1[Din x F] ----
#pragma unroll
        for (int it = 0; it < 2; ++it) {
            int slot = it * NT + t;
            int kk = slot >> 5;             // 0..15
            int fg = slot & 31;
            int k = kt + kk;
            int f = f0 + fg * 4;
            float4 v = make_float4(0.f, 0.f, 0.f, 0.f);
            if (k < Din) {
                if (f + 3 < F) v = *reinterpret_cast<const float4*>(&W1[(size_t)k * F + f]);
                else {
                    if (f     < F) v.x = W1[(size_t)k * F + f];
                    if (f + 1 < F) v.y = W1[(size_t)k * F + f + 1];
                    if (f + 2 < F) v.z = W1[(size_t)k * F + f + 2];
                    if (f + 3 < F) v.w = W1[(size_t)k * F + f + 3];
                }
            }
            *reinterpret_cast<float4*>(&Bs[kk][fg * 4]) = v;
        }
        __syncthreads();
        // ---- compute 8x8 ----
#pragma unroll
        for (int k = 0; k < BK; ++k) {
            float4 a0 = *reinterpret_cast<const float4*>(&As[k][ty * 8]);
            float4 a1 = *reinterpret_cast<const float4*>(&As[k][ty * 8 + 4]);
            float4 c0 = *reinterpret_cast<const float4*>(&Bs[k][tx * 8]);
            float4 c1 = *reinterpret_cast<const float4*>(&Bs[k][tx * 8 + 4]);
            float av[8] = {a0.x,a0.y,a0.z,a0.w,a1.x,a1.y,a1.z,a1.w};
            float bv[8] = {c0.x,c0.y,c0.z,c0.w,c1.x,c1.y,c1.z,c1.w};
#pragma unroll
            for (int i = 0; i < 8; ++i)
#pragma unroll
                for (int j = 0; j < 8; ++j) acc[i][j] = fmaf(av[i], bv[j], acc[i][j]);
        }
        __syncthreads();
    }

    // ---- epilogue: bias + ReLU + BN1-stat partials + scatter max/min ----
    float bb[8], gg[8];
#pragma unroll
    for (int j = 0; j < 8; ++j) {
        int f = f0 + tx * 8 + j;
        bb[j] = (f < F) ? b1[f] : 0.f;
        gg[j] = (f < F) ? g1[f] : 1.f;
    }
#pragma unroll
    for (int j = 0; j < 8; ++j) {
        int f = f0 + tx * 8 + j;
        if (f >= F) continue;
        float s = 0.f, s2 = 0.f;
        bool pos = (gg[j] >= 0.f);
#pragma unroll
        for (int i = 0; i < 8; ++i) {
            int ei = ty * 8 + i;
            int e  = e0 + ei;
            if (e >= E) continue;
            float z = fmaxf(acc[i][j] + bb[j], 0.f);
            s += z; s2 += z * z;
            int* addr = (int*)&g_nodebuf[(size_t)sC[ei] * F + f];
            // z >= 0: int-bit ordering == float ordering
            if (pos) atomicMax(addr, __float_as_int(z));
            else     atomicMin(addr, __float_as_int(z));
        }
        atomicAdd(&sSum[tx * 8 + j], s);
        atomicAdd(&sSq [tx * 8 + j], s2);
    }
    __syncthreads();
    for (int i = t; i < BF; i += NT) {
        int f = f0 + i;
        if (f < F) {
            atomicAdd(&g_sums [f], sSum[i]);
            atomicAdd(&g_sumsq[f], sSq[i]);
        }
    }
}

// ---------------- finalize BN stats -> affine (scale, shift) ----------------
__global__ void k_stats(const float* __restrict__ g, const float* __restrict__ be,
                        float invN, int F, int which) {
    int f = blockIdx.x * blockDim.x + threadIdx.x;
    if (f >= F) return;
    float s  = which ? g_sums2[f]  : g_sums[f];
    float sq = which ? g_sumsq2[f] : g_sumsq[f];
    float mean = s * invN;
    float var  = fmaxf(sq * invN - mean * mean, 0.f);
    float rstd = rsqrtf(var + 1e-5f);
    float sc = g[f] * rstd;
    float sh = be[f] - mean * sc;
    if (which) { g_scale2[f] = sc; g_shift2[f] = sh; }
    else       { g_scale1[f] = sc; g_shift1[f] = sh; }
}

// ---------------- node GEMM: BN1(agg) on the fly -> @W2 -> ReLU -> stats ----------------
__global__ __launch_bounds__(NT, 2)
void k_node(const float* __restrict__ W2, const float* __restrict__ b2,
            int NCur, int F)
{
    __shared__ float As[BK][BE];
    __shared__ float Bs[BK][BF + 4];
    __shared__ int   sFlag[BE];
    __shared__ float sSum[BF], sSq[BF];

    const int t  = threadIdx.x;
    const int n0 = blockIdx.x * BE;
    const int f0 = blockIdx.y * BF;

    for (int i = t; i < BE; i += NT) {
        int n = n0 + i;
        sFlag[i] = (n < NCur) ? g_flags[n] : 0;
    }
    for (int i = t; i < BF; i += NT) { sSum[i] = 0.f; sSq[i] = 0.f; }
    __syncthreads();

    float acc[8][8];
#pragma unroll
    for (int i = 0; i < 8; ++i)
#pragma unroll
        for (int j = 0; j < 8; ++j) acc[i][j] = 0.f;

    const int tx = t & 15, ty = t >> 4;
    const int nTiles = (F + BK - 1) / BK;
    for (int kt0 = 0; kt0 < nTiles; ++kt0) {
        const int kt = kt0 * BK;
        const bool full = (kt + BK <= F);
#pragma unroll
        for (int it = 0; it < 2; ++it) {
            int slot = it * NT + t;
            int i  = slot & (BE - 1);
            int kg = slot >> 7;
            int k  = kt + kg * 4;
            int n  = n0 + i;
            float4 v = make_float4(0.f, 0.f, 0.f, 0.f);
            if (n < NCur && sFlag[i]) {
                if (full) {
                    float4 raw = *reinterpret_cast<const float4*>(&g_nodebuf[(size_t)n * F + k]);
                    v.x = g_scale1[k]   * raw.x + g_shift1[k];
                    v.y = g_scale1[k+1] * raw.y + g_shift1[k+1];
                    v.z = g_scale1[k+2] * raw.z + g_shift1[k+2];
                    v.w = g_scale1[k+3] * raw.w + g_shift1[k+3];
                } else {
                    if (k   < F) v.x = g_scale1[k]  * g_nodebuf[(size_t)n*F+k]   + g_shift1[k];
                    if (k+1 < F) v.y = g_scale1[k+1]* g_nodebuf[(size_t)n*F+k+1] + g_shift1[k+1];
                    if (k+2 < F) v.z = g_scale1[k+2]* g_nodebuf[(size_t)n*F+k+2] + g_shift1[k+2];
                    if (k+3 < F) v.w = g_scale1[k+3]* g_nodebuf[(size_t)n*F+k+3] + g_shift1[k+3];
                }
            }
            As[kg*4+0][i] = v.x; As[kg*4+1][i] = v.y;
            As[kg*4+2][i] = v.z; As[kg*4+3][i] = v.w;
        }
#pragma unroll
        for (int it = 0; it < 2; ++it) {
            int slot = it * NT + t;
            int kk = slot >> 5;
            int fg = slot & 31;
            int k = kt + kk;
            int f = f0 + fg * 4;
            float4 v = make_float4(0.f, 0.f, 0.f, 0.f);
            if (k < F) {
                if (f + 3 < F) v = *reinterpret_cast<const float4*>(&W2[(size_t)k * F + f]);
                else {
                    if (f     < F) v.x = W2[(size_t)k * F + f];
                    if (f + 1 < F) v.y = W2[(size_t)k * F + f + 1];
                    if (f + 2 < F) v.z = W2[(size_t)k * F + f + 2];
                    if (f + 3 < F) v.w = W2[(size_t)k * F + f + 3];
                }
            }
            *reinterpret_cast<float4*>(&Bs[kk][fg * 4]) = v;
        }
        __syncthreads();
#pragma unroll
        for (int k = 0; k < BK; ++k) {
            float4 a0 = *reinterpret_cast<const float4*>(&As[k][ty * 8]);
            float4 a1 = *reinterpret_cast<const float4*>(&As[k][ty * 8 + 4]);
            float4 c0 = *reinterpret_cast<const float4*>(&Bs[k][tx * 8]);
            float4 c1 = *reinterpret_cast<const float4*>(&Bs[k][tx * 8 + 4]);
            float av[8] = {a0.x,a0.y,a0.z,a0.w,a1.x,a1.y,a1.z,a1.w};
            float bv[8] = {c0.x,c0.y,c0.z,c0.w,c1.x,c1.y,c1.z,c1.w};
#pragma unroll
            for (int i = 0; i < 8; ++i)
#pragma unroll
                for (int j = 0; j < 8; ++j) acc[i][j] = fmaf(av[i], bv[j], acc[i][j]);
        }
        __syncthreads();
    }

    float bb[8];
#pragma unroll
    for (int j = 0; j < 8; ++j) {
        int f = f0 + tx * 8 + j;
        bb[j] = (f < F) ? b2[f] : 0.f;
    }
#pragma unroll
    for (int j = 0; j < 8; ++j) {
        int f = f0 + tx * 8 + j;
        if (f >= F) continue;
        float s = 0.f, s2 = 0.f;
#pragma unroll
        for (int i = 0; i < 8; ++i) {
            int n = n0 + ty * 8 + i;
            if (n >= NCur) continue;
            float z = fmaxf(acc[i][j] + bb[j], 0.f);
            g_outpre[(size_t)n * F + f] = z;
            s += z; s2 += z * z;
        }
        atomicAdd(&sSum[tx * 8 + j], s);
        atomicAdd(&sSq [tx * 8 + j], s2);
    }
    __syncthreads();
    for (int i = t; i < BF; i += NT) {
        int f = f0 + i;
        if (f < F) {
            atomicAdd(&g_sums2 [f], sSum[i]);
            atomicAdd(&g_sumsq2[f], sSq[i]);
        }
    }
}

// ---------------- apply BN2 ----------------
__global__ void k_apply(float* __restrict__ out, int NCur, int F) {
    int total = NCur * F;
    for (int idx = blockIdx.x * blockDim.x + threadIdx.x; idx < total;
         idx += gridDim.x * blockDim.x) {
        int f = idx % F;
        out[idx] = g_scale2[f] * g_outpre[idx] + g_shift2[f];
    }
}

// ---------------- launch ----------------
extern "C" void kernel_launch(void* const* d_in, const int* in_sizes, int n_in,
                              void* d_out, int out_size) {
    const float* last_coors    = (const float*)d_in[0];
    const float* last_features = (const float*)d_in[1];
    const float* current_coors = (const float*)d_in[2];
    const int*   cur_idx       = (const int*)  d_in[3];
    const int*   last_idx      = (const int*)  d_in[4];
    const float* W1  = (const float*)d_in[5];
    const float* b1  = (const float*)d_in[6];
    const float* g1  = (const float*)d_in[7];
    const float* be1 = (const float*)d_in[8];
    const float* W2  = (const float*)d_in[9];
    const float* b2  = (const float*)d_in[10];
    const float* g2  = (const float*)d_in[11];
    const float* be2 = (const float*)d_in[12];

    const int F    = in_sizes[6];          // 300
    const int NCur = in_sizes[2] / 3;      // 50000
    const int E    = in_sizes[3];          // 500000
    float* out = (float*)d_out;

    {
        int total = NCur * F;
        int nb = (total + 255) / 256;
        k_init<<<nb, 256>>>(g1, NCur, F);
    }
    k_flag<<<(E + 255) / 256, 256>>>(cur_idx, E);

    dim3 gE((E + BE - 1) / BE, (F + BF - 1) / BF);
    k_edge<<<gE, NT>>>(last_features, last_coors, current_coors,
                       cur_idx, last_idx, W1, b1, g1, E, F, NCur);

    k_stats<<<(F + 255) / 256, 256>>>(g1, be1, 1.0f / (float)E, F, 0);

    dim3 gN((NCur + BE - 1) / BE, (F + BF - 1) / BF);
    k_node<<<gN, NT>>>(W2, b2, NCur, F);

    k_stats<<<(F + 255) / 256, 256>>>(g2, be2, 1.0f / (float)NCur, F, 1);

    k_apply<<<(NCur * F + 255) / 256, 256>>>(out, NCur, F);
}

// round 4
// speedup vs baseline: 2.1643x; 2.1643x over previous
#include <cuda_runtime.h>
#include <cfloat>

// ---------------- static scratch (no allocations allowed) ----------------
#define MAX_NF    15200000   // >= N_cur * F = 50000*300
#define MAX_LF    30400000   // >= N_last * F = 100000*300
#define MAX_NODE  50048
#define MAX_F     304

__device__ float g_nodebuf[MAX_NF];   // per-(node,feat) running max (or min) of z
__device__ float g_outpre[MAX_NF];    // ReLU(agg@W2+b2) before BN2
__device__ float g_pq[MAX_LF];        // lastAug @ W1 + b1  [N_last, F]
__device__ float g_r[MAX_NF];         // curC @ W1c          [N_cur, F]
__device__ int   g_flags[MAX_NODE];   // node has >=1 edge
__device__ float g_sums[MAX_F],  g_sumsq[MAX_F];   // BN1 stats
__device__ float g_sums2[MAX_F], g_sumsq2[MAX_F];  // BN2 stats
__device__ float g_scale1[MAX_F], g_shift1[MAX_F];
__device__ float g_scale2[MAX_F], g_shift2[MAX_F];

#define BE 128
#define BF 128
#define BK 16
#define NT 256

// ---------------- init: nodebuf per sign(g1), flags, stat accumulators ----------------
__global__ void k_init(const float* __restrict__ g1, int NCur, int F) {
    int total = NCur * F;
    int tid = blockIdx.x * blockDim.x + threadIdx.x;
    for (int idx = tid; idx < total; idx += gridDim.x * blockDim.x) {
        int f = idx % F;
        g_nodebuf[idx] = (g1[f] >= 0.f) ? 0.f : FLT_MAX;  // z >= 0 always (post-ReLU)
    }
    if (tid < NCur) g_flags[tid] = 0;
    if (tid < F) { g_sums[tid]=0.f; g_sumsq[tid]=0.f; g_sums2[tid]=0.f; g_sumsq2[tid]=0.f; }
}

__global__ void k_flag(const int* __restrict__ cur_idx, int E) {
    int e = blockIdx.x * blockDim.x + threadIdx.x;
    if (e < E) g_flags[cur_idx[e]] = 1;   // benign race, same value
}

// ---------------- PQ GEMM: [lastF | lastC] @ W1 + b1 over last nodes ----------------
__global__ __launch_bounds__(NT, 2)
void k_pq(const float* __restrict__ lastF, const float* __restrict__ lastC,
          const float* __restrict__ W1, const float* __restrict__ b1,
          int NLast, int F)
{
    const int Din = F + 3;
    __shared__ float As[BK][BE];
    __shared__ float Bs[BK][BF + 4];

    const int t  = threadIdx.x;
    const int m0 = blockIdx.x * BE;
    const int f0 = blockIdx.y * BF;

    float acc[8][8];
#pragma unroll
    for (int i = 0; i < 8; ++i)
#pragma unroll
        for (int j = 0; j < 8; ++j) acc[i][j] = 0.f;

    const int tx = t & 15;
    const int ty = t >> 4;

    const int nTiles = (Din + BK - 1) / BK;
    for (int kt0 = 0; kt0 < nTiles; ++kt0) {
        const int kt = kt0 * BK;
        if (kt + BK <= F) {                 // pure-feature tile, vector path
#pragma unroll
            for (int it = 0; it < 2; ++it) {
                int slot = it * NT + t;
                int i  = slot & (BE - 1);
                int kg = slot >> 7;
                int m  = m0 + i;
                float4 v = make_float4(0.f,0.f,0.f,0.f);
                if (m < NLast)
                    v = *reinterpret_cast<const float4*>(&lastF[(size_t)m * F + kt + kg * 4]);
                As[kg*4+0][i] = v.x; As[kg*4+1][i] = v.y;
                As[kg*4+2][i] = v.z; As[kg*4+3][i] = v.w;
            }
        } else {                            // boundary tile (features + coords)
            for (int slot = t; slot < BE * BK; slot += NT) {
                int i  = slot & (BE - 1);
                int kk = slot >> 7;
                int k  = kt + kk;
                int m  = m0 + i;
                float v = 0.f;
                if (m < NLast) {
                    if (k < F)        v = lastF[(size_t)m * F + k];
                    else if (k < Din) v = lastC[m*3 + (k - F)];
                }
                As[kk][i] = v;
            }
        }
#pragma unroll
        for (int it = 0; it < 2; ++it) {
            int slot = it * NT + t;
            int kk = slot >> 5;
            int fg = slot & 31;
            int k = kt + kk;
            int f = f0 + fg * 4;
            float4 v = make_float4(0.f, 0.f, 0.f, 0.f);
            if (k < Din) {
                if (f + 3 < F) v = *reinterpret_cast<const float4*>(&W1[(size_t)k * F + f]);
                else {
                    if (f     < F) v.x = W1[(size_t)k * F + f];
                    if (f + 1 < F) v.y = W1[(size_t)k * F + f + 1];
                    if (f + 2 < F) v.z = W1[(size_t)k * F + f + 2];
                    if (f + 3 < F) v.w = W1[(size_t)k * F + f + 3];
                }
            }
            *reinterpret_cast<float4*>(&Bs[kk][fg * 4]) = v;
        }
        __syncthreads();
#pragma unroll
        for (int k = 0; k < BK; ++k) {
            float4 a0 = *reinterpret_cast<const float4*>(&As[k][ty * 8]);
            float4 a1 = *reinterpret_cast<const float4*>(&As[k][ty * 8 + 4]);
            float4 c0 = *reinterpret_cast<const float4*>(&Bs[k][tx * 8]);
            float4 c1 = *reinterpret_cast<const float4*>(&Bs[k][tx * 8 + 4]);
            float av[8] = {a0.x,a0.y,a0.z,a0.w,a1.x,a1.y,a1.z,a1.w};
            float bv[8] = {c0.x,c0.y,c0.z,c0.w,c1.x,c1.y,c1.z,c1.w};
#pragma unroll
            for (int i = 0; i < 8; ++i)
#pragma unroll
                for (int j = 0; j < 8; ++j) acc[i][j] = fmaf(av[i], bv[j], acc[i][j]);
        }
        __syncthreads();
    }

#pragma unroll
    for (int j = 0; j < 8; ++j) {
        int f = f0 + tx * 8 + j;
        if (f >= F) continue;
        float bb = b1[f];
#pragma unroll
        for (int i = 0; i < 8; ++i) {
            int m = m0 + ty * 8 + i;
            if (m < NLast) g_pq[(size_t)m * F + f] = acc[i][j] + bb;
        }
    }
}

// ---------------- R = curC @ W1c (3xF, tiny) ----------------
__global__ void k_r(const float* __restrict__ curC, const float* __restrict__ W1,
                    int NCur, int F)
{
    int total = NCur * F;
    for (int idx = blockIdx.x * blockDim.x + threadIdx.x; idx < total;
         idx += gridDim.x * blockDim.x) {
        int n = idx / F;
        int f = idx - n * F;
        float c0 = curC[n*3+0], c1 = curC[n*3+1], c2 = curC[n*3+2];
        float r = c0 * W1[(size_t)(F+0) * F + f]
                + c1 * W1[(size_t)(F+1) * F + f]
                + c2 * W1[(size_t)(F+2) * F + f];
        g_r[idx] = r;
    }
}

// ---------------- edge stage: gather -> sub -> ReLU -> stats + scatter max/min ----------------
#define ESB 256
#define ETHREADS 320
__global__ __launch_bounds__(ETHREADS)
void k_edge2(const int* __restrict__ cur_idx, const int* __restrict__ last_idx,
             const float* __restrict__ g1, int E, int F)
{
    __shared__ int sL[ESB], sC[ESB];
    const int t = threadIdx.x;
    const int f = t;
    const bool act = (f < F);
    const bool pos = act ? (g1[f] >= 0.f) : true;

    float ssum = 0.f, ssq = 0.f;

    for (int base = blockIdx.x * ESB; base < E; base += gridDim.x * ESB) {
        int cnt = min(ESB, E - base);
        __syncthreads();
        for (int i = t; i < cnt; i += ETHREADS) {
            sL[i] = last_idx[base + i];
            sC[i] = cur_idx[base + i];
        }
        __syncthreads();
        if (act) {
#pragma unroll 4
            for (int i = 0; i < cnt; ++i) {
                const float pq = __ldg(&g_pq[(size_t)sL[i] * F + f]);
                const float r  = __ldg(&g_r [(size_t)sC[i] * F + f]);
                const float z  = fmaxf(pq - r, 0.f);
                ssum += z; ssq += z * z;
                int* addr = (int*)&g_nodebuf[(size_t)sC[i] * F + f];
                const int zi = __float_as_int(z);   // z>=0: int order == float order
                const int cur = *((volatile int*)addr);
                if (pos) { if (zi > cur) atomicMax(addr, zi); }
                else     { if (zi < cur) atomicMin(addr, zi); }
            }
        }
    }
    if (act) {
        atomicAdd(&g_sums [f], ssum);
        atomicAdd(&g_sumsq[f], ssq);
    }
}

// ---------------- finalize BN stats -> affine (scale, shift) ----------------
__global__ void k_stats(const float* __restrict__ g, const float* __restrict__ be,
                        float invN, int F, int which) {
    int f = blockIdx.x * blockDim.x + threadIdx.x;
    if (f >= F) return;
    float s  = which ? g_sums2[f]  : g_sums[f];
    float sq = which ? g_sumsq2[f] : g_sumsq[f];
    float mean = s * invN;
    float var  = fmaxf(sq * invN - mean * mean, 0.f);
    float rstd = rsqrtf(var + 1e-5f);
    float sc = g[f] * rstd;
    float sh = be[f] - mean * sc;
    if (which) { g_scale2[f] = sc; g_shift2[f] = sh; }
    else       { g_scale1[f] = sc; g_shift1[f] = sh; }
}

// ---------------- node GEMM: BN1(agg) on the fly -> @W2 -> ReLU -> stats ----------------
__global__ __launch_bounds__(NT, 2)
void k_node(const float* __restrict__ W2, const float* __restrict__ b2,
            int NCur, int F)
{
    __shared__ float As[BK][BE];
    __shared__ float Bs[BK][BF + 4];
    __shared__ int   sFlag[BE];
    __shared__ float sSum[BF], sSq[BF];

    const int t  = threadIdx.x;
    const int n0 = blockIdx.x * BE;
    const int f0 = blockIdx.y * BF;

    for (int i = t; i < BE; i += NT) {
        int n = n0 + i;
        sFlag[i] = (n < NCur) ? g_flags[n] : 0;
    }
    for (int i = t; i < BF; i += NT) { sSum[i] = 0.f; sSq[i] = 0.f; }
    __syncthreads();

    float acc[8][8];
#pragma unroll
    for (int i = 0; i < 8; ++i)
#pragma unroll
        for (int j = 0; j < 8; ++j) acc[i][j] = 0.f;

    const int tx = t & 15, ty = t >> 4;
    const int nTiles = (F + BK - 1) / BK;
    for (int kt0 = 0; kt0 < nTiles; ++kt0) {
        const int kt = kt0 * BK;
        const bool full = (kt + BK <= F);
#pragma unroll
        for (int it = 0; it < 2; ++it) {
            int slot = it * NT + t;
            int i  = slot & (BE - 1);
            int kg = slot >> 7;
            int k  = kt + kg * 4;
            int n  = n0 + i;
            float4 v = make_float4(0.f, 0.f, 0.f, 0.f);
            if (n < NCur && sFlag[i]) {
                if (full) {
                    float4 raw = *reinterpret_cast<const float4*>(&g_nodebuf[(size_t)n * F + k]);
                    v.x = g_scale1[k]   * raw.x + g_shift1[k];
                    v.y = g_scale1[k+1] * raw.y + g_shift1[k+1];
                    v.z = g_scale1[k+2] * raw.z + g_shift1[k+2];
                    v.w = g_scale1[k+3] * raw.w + g_shift1[k+3];
                } else {
                    if (k   < F) v.x = g_scale1[k]  * g_nodebuf[(size_t)n*F+k]   + g_shift1[k];
                    if (k+1 < F) v.y = g_scale1[k+1]* g_nodebuf[(size_t)n*F+k+1] + g_shift1[k+1];
                    if (k+2 < F) v.z = g_scale1[k+2]* g_nodebuf[(size_t)n*F+k+2] + g_shift1[k+2];
                    if (k+3 < F) v.w = g_scale1[k+3]* g_nodebuf[(size_t)n*F+k+3] + g_shift1[k+3];
                }
            }
            As[kg*4+0][i] = v.x; As[kg*4+1][i] = v.y;
            As[kg*4+2][i] = v.z; As[kg*4+3][i] = v.w;
        }
#pragma unroll
        for (int it = 0; it < 2; ++it) {
            int slot = it * NT + t;
            int kk = slot >> 5;
            int fg = slot & 31;
            int k = kt + kk;
            int f = f0 + fg * 4;
            float4 v = make_float4(0.f, 0.f, 0.f, 0.f);
            if (k < F) {
                if (f + 3 < F) v = *reinterpret_cast<const float4*>(&W2[(size_t)k * F + f]);
                else {
                    if (f     < F) v.x = W2[(size_t)k * F + f];
                    if (f + 1 < F) v.y = W2[(size_t)k * F + f + 1];
                    if (f + 2 < F) v.z = W2[(size_t)k * F + f + 2];
                    if (f + 3 < F) v.w = W2[(size_t)k * F + f + 3];
                }
            }
            *reinterpret_cast<float4*>(&Bs[kk][fg * 4]) = v;
        }
        __syncthreads();
#pragma unroll
        for (int k = 0; k < BK; ++k) {
            float4 a0 = *reinterpret_cast<const float4*>(&As[k][ty * 8]);
            float4 a1 = *reinterpret_cast<const float4*>(&As[k][ty * 8 + 4]);
            float4 c0 = *reinterpret_cast<const float4*>(&Bs[k][tx * 8]);
            float4 c1 = *reinterpret_cast<const float4*>(&Bs[k][tx * 8 + 4]);
            float av[8] = {a0.x,a0.y,a0.z,a0.w,a1.x,a1.y,a1.z,a1.w};
            float bv[8] = {c0.x,c0.y,c0.z,c0.w,c1.x,c1.y,c1.z,c1.w};
#pragma unroll
            for (int i = 0; i < 8; ++i)
#pragma unroll
                for (int j = 0; j < 8; ++j) acc[i][j] = fmaf(av[i], bv[j], acc[i][j]);
        }
        __syncthreads();
    }

    float bb[8];
#pragma unroll
    for (int j = 0; j < 8; ++j) {
        int f = f0 + tx * 8 + j;
        bb[j] = (f < F) ? b2[f] : 0.f;
    }
#pragma unroll
    for (int j = 0; j < 8; ++j) {
        int f = f0 + tx * 8 + j;
        if (f >= F) continue;
        float s = 0.f, s2 = 0.f;
#pragma unroll
        for (int i = 0; i < 8; ++i) {
            int n = n0 + ty * 8 + i;
            if (n >= NCur) continue;
            float z = fmaxf(acc[i][j] + bb[j], 0.f);
            g_outpre[(size_t)n * F + f] = z;
            s += z; s2 += z * z;
        }
        atomicAdd(&sSum[tx * 8 + j], s);
        atomicAdd(&sSq [tx * 8 + j], s2);
    }
    __syncthreads();
    for (int i = t; i < BF; i += NT) {
        int f = f0 + i;
        if (f < F) {
            atomicAdd(&g_sums2 [f], sSum[i]);
            atomicAdd(&g_sumsq2[f], sSq[i]);
        }
    }
}

// ---------------- apply BN2 ----------------
__global__ void k_apply(float* __restrict__ out, int NCur, int F) {
    int total = NCur * F;
    for (int idx = blockIdx.x * blockDim.x + threadIdx.x; idx < total;
         idx += gridDim.x * blockDim.x) {
        int f = idx % F;
        out[idx] = g_scale2[f] * g_outpre[idx] + g_shift2[f];
    }
}

// ---------------- launch ----------------
extern "C" void kernel_launch(void* const* d_in, const int* in_sizes, int n_in,
                              void* d_out, int out_size) {
    const float* last_coors    = (const float*)d_in[0];
    const float* last_features = (const float*)d_in[1];
    const float* current_coors = (const float*)d_in[2];
    const int*   cur_idx       = (const int*)  d_in[3];
    const int*   last_idx      = (const int*)  d_in[4];
    const float* W1  = (const float*)d_in[5];
    const float* b1  = (const float*)d_in[6];
    const float* g1  = (const float*)d_in[7];
    const float* be1 = (const float*)d_in[8];
    const float* W2  = (const float*)d_in[9];
    const float* b2  = (const float*)d_in[10];
    const float* g2  = (const float*)d_in[11];
    const float* be2 = (const float*)d_in[12];

    const int F     = in_sizes[6];          // 300
    const int NCur  = in_sizes[2] / 3;      // 50000
    const int NLast = in_sizes[0] / 3;      // 100000
    const int E     = in_sizes[3];          // 500000
    float* out = (float*)d_out;

    {
        int total = NCur * F;
        int nb = (total + 255) / 256;
        k_init<<<nb, 256>>>(g1, NCur, F);
    }
    k_flag<<<(E + 255) / 256, 256>>>(cur_idx, E);

    // PQ = [lastF | lastC] @ W1 + b1   (18.2 GFLOP, the new dominant GEMM)
    dim3 gP((NLast + BE - 1) / BE, (F + BF - 1) / BF);
    k_pq<<<gP, NT>>>(last_features, last_coors, W1, b1, NLast, F);

    // R = curC @ W1c (tiny)
    k_r<<<2048, 256>>>(current_coors, W1, NCur, F);

    // edge gather/subtract/relu/scatter-max + BN1 stats
    k_edge2<<<148 * 8, ETHREADS>>>(cur_idx, last_idx, g1, E, F);

    k_stats<<<(F + 255) / 256, 256>>>(g1, be1, 1.0f / (float)E, F, 0);

    dim3 gN((NCur + BE - 1) / BE, (F + BF - 1) / BF);
    k_node<<<gN, NT>>>(W2, b2, NCur, F);

    k_stats<<<(F + 255) / 256, 256>>>(g2, be2, 1.0f / (float)NCur, F, 1);

    k_apply<<<(NCur * F + 255) / 256, 256>>>(out, NCur, F);
}

// round 9
// speedup vs baseline: 2.8936x; 1.3370x over previous
#include <cuda_runtime.h>
#include <cuda_bf16.h>
#include <cfloat>
#include <cstdint>

// ================= static scratch =================
#define MAX_NF    15200000   // >= N_cur * F
#define MAX_LF    30400000   // >= N_last * F
#define MAX_NODE  50048
#define MAX_F     304
#define KPAD      320        // padded K (5 chunks of 64)
#define NPADW     384        // padded N rows for weight-transpose buffers
#define APAD_ROWS 100096     // 782*128

__device__ float g_nodebuf[MAX_NF];
__device__ float g_outpre[MAX_NF];
__device__ float g_pq[MAX_LF];
__device__ float g_r[MAX_NF];
__device__ int   g_flags[MAX_NODE];
__device__ float g_sums[MAX_F],  g_sumsq[MAX_F];
__device__ float g_sums2[MAX_F], g_sumsq2[MAX_F];
__device__ float g_scale1[MAX_F], g_shift1[MAX_F];
__device__ float g_scale2[MAX_F], g_shift2[MAX_F];

__device__ __align__(16) __nv_bfloat16 g_Ah[(size_t)APAD_ROWS * KPAD];
__device__ __align__(16) __nv_bfloat16 g_Al[(size_t)APAD_ROWS * KPAD];
__device__ __align__(16) __nv_bfloat16 g_Wh[NPADW * KPAD];
__device__ __align__(16) __nv_bfloat16 g_Wl[NPADW * KPAD];

// ================= small kernels =================
__global__ void k_init(const float* __restrict__ g1, int NCur, int F) {
    int total = NCur * F;
    int tid = blockIdx.x * blockDim.x + threadIdx.x;
    for (int idx = tid; idx < total; idx += gridDim.x * blockDim.x) {
        int f = idx % F;
        g_nodebuf[idx] = (g1[f] >= 0.f) ? 0.f : FLT_MAX;
    }
    if (tid < NCur) g_flags[tid] = 0;
    if (tid < F) { g_sums[tid]=0.f; g_sumsq[tid]=0.f; g_sums2[tid]=0.f; g_sumsq2[tid]=0.f; }
}

__global__ void k_flag(const int* __restrict__ cur_idx, int E) {
    int e = blockIdx.x * blockDim.x + threadIdx.x;
    if (e < E) g_flags[cur_idx[e]] = 1;
}

// fp32 -> bf16 hi/lo split of [lastF | lastC], padded [rowsPad x KPAD]
__global__ void k_convA_pq(const float* __restrict__ lastF, const float* __restrict__ lastC,
                           int NLast, int F, int rowsPad) {
    size_t total = (size_t)rowsPad * KPAD;
    for (size_t idx = (size_t)blockIdx.x * blockDim.x + threadIdx.x; idx < total;
         idx += (size_t)gridDim.x * blockDim.x) {
        int m = (int)(idx / KPAD);
        int k = (int)(idx - (size_t)m * KPAD);
        float v = 0.f;
        if (m < NLast) {
            if (k < F)          v = lastF[(size_t)m * F + k];
            else if (k < F + 3) v = lastC[m * 3 + (k - F)];
        }
        __nv_bfloat16 hi = __float2bfloat16(v);
        g_Ah[idx] = hi;
        g_Al[idx] = __float2bfloat16(v - __bfloat162float(hi));
    }
}

// transpose+split W [Kvalid x F] -> Wt hi/lo [NPADW x KPAD] (n-major)
__global__ void k_convW(const float* __restrict__ W, int Kvalid, int F) {
    int total = NPADW * KPAD;
    for (int idx = blockIdx.x * blockDim.x + threadIdx.x; idx < total;
         idx += gridDim.x * blockDim.x) {
        int n = idx / KPAD;
        int k = idx - n * KPAD;
        float v = (n < F && k < Kvalid) ? W[(size_t)k * F + n] : 0.f;
        __nv_bfloat16 hi = __float2bfloat16(v);
        g_Wh[idx] = hi;
        g_Wl[idx] = __float2bfloat16(v - __bfloat162float(hi));
    }
}

// BN1(agg) -> bf16 hi/lo, padded rows
__global__ void k_convA_node(int NCur, int F, int rowsPad) {
    size_t total = (size_t)rowsPad * KPAD;
    for (size_t idx = (size_t)blockIdx.x * blockDim.x + threadIdx.x; idx < total;
         idx += (size_t)gridDim.x * blockDim.x) {
        int n = (int)(idx / KPAD);
        int k = (int)(idx - (size_t)n * KPAD);
        float v = 0.f;
        if (n < NCur && k < F && g_flags[n])
            v = g_scale1[k] * g_nodebuf[(size_t)n * F + k] + g_shift1[k];
        __nv_bfloat16 hi = __float2bfloat16(v);
        g_Ah[idx] = hi;
        g_Al[idx] = __float2bfloat16(v - __bfloat162float(hi));
    }
}

// R = curC @ W1c
__global__ void k_r(const float* __restrict__ curC, const float* __restrict__ W1,
                    int NCur, int F) {
    int total = NCur * F;
    for (int idx = blockIdx.x * blockDim.x + threadIdx.x; idx < total;
         idx += gridDim.x * blockDim.x) {
        int n = idx / F;
        int f = idx - n * F;
        float c0 = curC[n*3+0], c1 = curC[n*3+1], c2 = curC[n*3+2];
        g_r[idx] = c0 * W1[(size_t)(F+0) * F + f]
                 + c1 * W1[(size_t)(F+1) * F + f]
                 + c2 * W1[(size_t)(F+2) * F + f];
    }
}

// ================= edge stage =================
#define ESB 256
#define ETHREADS 320
__global__ __launch_bounds__(ETHREADS)
void k_edge2(const int* __restrict__ cur_idx, const int* __restrict__ last_idx,
             const float* __restrict__ g1, int E, int F)
{
    __shared__ int sL[ESB], sC[ESB];
    const int t = threadIdx.x;
    const int f = t;
    const bool act = (f < F);
    const bool pos = act ? (g1[f] >= 0.f) : true;

    float ssum = 0.f, ssq = 0.f;

    for (int base = blockIdx.x * ESB; base < E; base += gridDim.x * ESB) {
        int cnt = min(ESB, E - base);
        __syncthreads();
        for (int i = t; i < cnt; i += ETHREADS) {
            sL[i] = last_idx[base + i];
            sC[i] = cur_idx[base + i];
        }
        __syncthreads();
        if (act) {
#pragma unroll 4
            for (int i = 0; i < cnt; ++i) {
                const float pq = __ldg(&g_pq[(size_t)sL[i] * F + f]);
                const float r  = __ldg(&g_r [(size_t)sC[i] * F + f]);
                const float z  = fmaxf(pq - r, 0.f);
                ssum += z; ssq += z * z;
                int* addr = (int*)&g_nodebuf[(size_t)sC[i] * F + f];
                const int zi = __float_as_int(z);
                const int cur = *((volatile int*)addr);
                if (pos) { if (zi > cur) atomicMax(addr, zi); }
                else     { if (zi < cur) atomicMin(addr, zi); }
            }
        }
    }
    if (act) {
        atomicAdd(&g_sums [f], ssum);
        atomicAdd(&g_sumsq[f], ssq);
    }
}

// ================= BN stats finalize =================
__global__ void k_stats(const float* __restrict__ g, const float* __restrict__ be,
                        float invN, int F, int which) {
    int f = blockIdx.x * blockDim.x + threadIdx.x;
    if (f >= F) return;
    float s  = which ? g_sums2[f]  : g_sums[f];
    float sq = which ? g_sumsq2[f] : g_sumsq[f];
    float mean = s * invN;
    float var  = fmaxf(sq * invN - mean * mean, 0.f);
    float rstd = rsqrtf(var + 1e-5f);
    float sc = g[f] * rstd;
    float sh = be[f] - mean * sc;
    if (which) { g_scale2[f] = sc; g_shift2[f] = sh; }
    else       { g_scale1[f] = sc; g_shift1[f] = sh; }
}

// ================= bf16-split HMMA GEMM (mma.sync, baseline PTX) =================
// C[M x N] = (Ah+Al) @ (Bh+Bl)^T, fp32 accumulate, 3 terms (drop lo*lo).
// Block tile 128x128, 8 warps (4 m x 2 n), warp tile 32x64.
// K chunks of 64 staged in SMEM with padded stride 72 bf16 (144B).
// NOTE: A/B/out bound to __device__ globals IN DEVICE CODE (host-side
// addresses of __device__ symbols are invalid-but-ATS-readable on GB300).
#define HM_NT 256
#define KC 64
#define SSTRIDE 72
#define TILE_B16 (128 * SSTRIDE)            // 9216 bf16 = 18432 B
#define SMEM_HMMA_BYTES (4 * TILE_B16 * 2)  // 73728 B

__device__ __forceinline__ void mma_bf16(float* d, const uint32_t* a, const uint32_t* b) {
    asm volatile(
        "mma.sync.aligned.m16n8k16.row.col.f32.bf16.bf16.f32 "
        "{%0,%1,%2,%3}, {%4,%5,%6,%7}, {%8,%9}, {%0,%1,%2,%3};"
        : "+f"(d[0]), "+f"(d[1]), "+f"(d[2]), "+f"(d[3])
        : "r"(a[0]), "r"(a[1]), "r"(a[2]), "r"(a[3]), "r"(b[0]), "r"(b[1]));
}

__global__ __launch_bounds__(HM_NT, 1)
void k_hmma(const float* __restrict__ bias, int Mvalid, int F, int mode)
{   // mode 0: +bias -> g_pq ; mode 1: relu+stats -> g_outpre
    const __nv_bfloat16* __restrict__ Ah = g_Ah;
    const __nv_bfloat16* __restrict__ Al = g_Al;
    const __nv_bfloat16* __restrict__ Bh = g_Wh;
    const __nv_bfloat16* __restrict__ Bl = g_Wl;
    float* __restrict__ outbuf = (mode == 0) ? g_pq : g_outpre;

    extern __shared__ __nv_bfloat16 sm[];
    __nv_bfloat16* sAh = sm;
    __nv_bfloat16* sAl = sm + TILE_B16;
    __nv_bfloat16* sBh = sm + 2 * TILE_B16;
    __nv_bfloat16* sBl = sm + 3 * TILE_B16;

    const int t    = threadIdx.x;
    const int wid  = t >> 5;
    const int lane = t & 31;
    const int gr   = lane >> 2;   // 0..7
    const int tg   = lane & 3;    // 0..3
    const int wm   = wid & 3;     // m-warp (32 rows)
    const int wn   = wid >> 2;    // n-warp (64 cols)

    const int m0 = blockIdx.x * 128;
    const int f0 = blockIdx.y * 128;

    float acc[2][8][4];
#pragma unroll
    for (int i = 0; i < 2; ++i)
#pragma unroll
        for (int j = 0; j < 8; ++j)
#pragma unroll
            for (int r = 0; r < 4; ++r) acc[i][j][r] = 0.f;

    for (int c = 0; c < KPAD / KC; ++c) {
#pragma unroll
        for (int w = 0; w < 4; ++w) {
            const __nv_bfloat16* src = (w == 0) ? Ah : (w == 1) ? Al : (w == 2) ? Bh : Bl;
            __nv_bfloat16* dst = (w == 0) ? sAh : (w == 1) ? sAl : (w == 2) ? sBh : sBl;
            const int rbase = (w < 2) ? m0 : f0;
#pragma unroll
            for (int it = 0; it < 4; ++it) {
                int slot = it * HM_NT + t;        // 0..1023
                int row = slot >> 3, q = slot & 7;
                const uint4 v = *reinterpret_cast<const uint4*>(
                    &src[(size_t)(rbase + row) * KPAD + c * KC + q * 8]);
                *reinterpret_cast<uint4*>(&dst[row * SSTRIDE + q * 8]) = v;
            }
        }
        __syncthreads();

#pragma unroll
        for (int kk = 0; kk < KC / 16; ++kk) {
            const int kb = kk * 16;
            uint32_t bh[8][2], bl[8][2];
#pragma unroll
            for (int na = 0; na < 8; ++na) {
                const int n = wn * 64 + na * 8 + gr;
                bh[na][0] = *reinterpret_cast<const uint32_t*>(&sBh[n * SSTRIDE + kb + tg * 2]);
                bh[na][1] = *reinterpret_cast<const uint32_t*>(&sBh[n * SSTRIDE + kb + 8 + tg * 2]);
                bl[na][0] = *reinterpret_cast<const uint32_t*>(&sBl[n * SSTRIDE + kb + tg * 2]);
                bl[na][1] = *reinterpret_cast<const uint32_t*>(&sBl[n * SSTRIDE + kb + 8 + tg * 2]);
            }
#pragma unroll
            for (int ma = 0; ma < 2; ++ma) {
                const int mr = wm * 32 + ma * 16 + gr;
                uint32_t ah[4], al[4];
                ah[0] = *reinterpret_cast<const uint32_t*>(&sAh[mr * SSTRIDE + kb + tg * 2]);
                ah[1] = *reinterpret_cast<const uint32_t*>(&sAh[(mr + 8) * SSTRIDE + kb + tg * 2]);
                ah[2] = *reinterpret_cast<const uint32_t*>(&sAh[mr * SSTRIDE + kb + 8 + tg * 2]);
                ah[3] = *reinterpret_cast<const uint32_t*>(&sAh[(mr + 8) * SSTRIDE + kb + 8 + tg * 2]);
                al[0] = *reinterpret_cast<const uint32_t*>(&sAl[mr * SSTRIDE + kb + tg * 2]);
                al[1] = *reinterpret_cast<const uint32_t*>(&sAl[(mr + 8) * SSTRIDE + kb + tg * 2]);
                al[2] = *reinterpret_cast<const uint32_t*>(&sAl[mr * SSTRIDE + kb + 8 + tg * 2]);
                al[3] = *reinterpret_cast<const uint32_t*>(&sAl[(mr + 8) * SSTRIDE + kb + 8 + tg * 2]);
#pragma unroll
                for (int na = 0; na < 8; ++na) {
                    mma_bf16(acc[ma][na], ah, bh[na]);
                    mma_bf16(acc[ma][na], ah, bl[na]);
                    mma_bf16(acc[ma][na], al, bh[na]);
                }
            }
        }
        __syncthreads();
    }

    // ---- epilogue ----
    float* sSum = (float*)sm;
    float* sSq  = (float*)sm + 128;
    if (mode == 1) {
        if (t < 128) { sSum[t] = 0.f; sSq[t] = 0.f; }
        __syncthreads();
    }

#pragma unroll
    for (int ma = 0; ma < 2; ++ma) {
#pragma unroll
        for (int na = 0; na < 8; ++na) {
            const int fc0 = wn * 64 + na * 8 + tg * 2;
            const int f_0 = f0 + fc0, f_1 = f_0 + 1;
            const int mA = m0 + wm * 32 + ma * 16 + gr;
            const int mB = mA + 8;
            float z0 = 0.f, z1 = 0.f, z2 = 0.f, z3 = 0.f;
            if (mode == 0) {
                if (f_0 < F) {
                    float b = bias[f_0];
                    if (mA < Mvalid) outbuf[(size_t)mA * F + f_0] = acc[ma][na][0] + b;
                    if (mB < Mvalid) outbuf[(size_t)mB * F + f_0] = acc[ma][na][2] + b;
                }
                if (f_1 < F) {
                    float b = bias[f_1];
                    if (mA < Mvalid) outbuf[(size_t)mA * F + f_1] = acc[ma][na][1] + b;
                    if (mB < Mvalid) outbuf[(size_t)mB * F + f_1] = acc[ma][na][3] + b;
                }
            } else {
                if (f_0 < F) {
                    float b = bias[f_0];
                    z0 = fmaxf(acc[ma][na][0] + b, 0.f);
                    z2 = fmaxf(acc[ma][na][2] + b, 0.f);
                    if (mA < Mvalid) outbuf[(size_t)mA * F + f_0] = z0; else z0 = 0.f;
                    if (mB < Mvalid) outbuf[(size_t)mB * F + f_0] = z2; else z2 = 0.f;
                }
                if (f_1 < F) {
                    float b = bias[f_1];
                    z1 = fmaxf(acc[ma][na][1] + b, 0.f);
                    z3 = fmaxf(acc[ma][na][3] + b, 0.f);
                    if (mA < Mvalid) outbuf[(size_t)mA * F + f_1] = z1; else z1 = 0.f;
                    if (mB < Mvalid) outbuf[(size_t)mB * F + f_1] = z3; else z3 = 0.f;
                }
                float s0 = z0 + z2, q0 = z0 * z0 + z2 * z2;
                float s1 = z1 + z3, q1 = z1 * z1 + z3 * z3;
#pragma unroll
                for (int off = 16; off >= 4; off >>= 1) {
                    s0 += __shfl_xor_sync(0xFFFFFFFFu, s0, off);
                    q0 += __shfl_xor_sync(0xFFFFFFFFu, q0, off);
                    s1 += __shfl_xor_sync(0xFFFFFFFFu, s1, off);
                    q1 += __shfl_xor_sync(0xFFFFFFFFu, q1, off);
                }
                if (gr == 0) {
                    atomicAdd(&sSum[fc0], s0);     atomicAdd(&sSq[fc0], q0);
                    atomicAdd(&sSum[fc0 + 1], s1); atomicAdd(&sSq[fc0 + 1], q1);
                }
            }
        }
    }
    if (mode == 1) {
        __syncthreads();
        if (t < 128) {
            int f = f0 + t;
            if (f < F) {
                atomicAdd(&g_sums2 [f], sSum[t]);
                atomicAdd(&g_sumsq2[f], sSq[t]);
            }
        }
    }
}

// ================= apply BN2 =================
__global__ void k_apply(float* __restrict__ out, int NCur, int F) {
    int total = NCur * F;
    for (int idx = blockIdx.x * blockDim.x + threadIdx.x; idx < total;
         idx += gridDim.x * blockDim.x) {
        int f = idx % F;
        out[idx] = g_scale2[f] * g_outpre[idx] + g_shift2[f];
    }
}

// ================= launch =================
extern "C" void kernel_launch(void* const* d_in, const int* in_sizes, int n_in,
                              void* d_out, int out_size) {
    const float* last_coors    = (const float*)d_in[0];
    const float* last_features = (const float*)d_in[1];
    const float* current_coors = (const float*)d_in[2];
    const int*   cur_idx       = (const int*)  d_in[3];
    const int*   last_idx      = (const int*)  d_in[4];
    const float* W1  = (const float*)d_in[5];
    const float* b1  = (const float*)d_in[6];
    const float* g1  = (const float*)d_in[7];
    const float* be1 = (const float*)d_in[8];
    const float* W2  = (const float*)d_in[9];
    const float* b2  = (const float*)d_in[10];
    const float* g2  = (const float*)d_in[11];
    const float* be2 = (const float*)d_in[12];

    const int F     = in_sizes[6];          // 300
    const int NCur  = in_sizes[2] / 3;      // 50000
    const int NLast = in_sizes[0] / 3;      // 100000
    const int E     = in_sizes[3];          // 500000
    float* out = (float*)d_out;

    cudaFuncSetAttribute(k_hmma, cudaFuncAttributeMaxDynamicSharedMemorySize, SMEM_HMMA_BYTES);

    const int mTilesPQ  = (NLast + 127) / 128;   // 782
    const int rowsPadPQ = mTilesPQ * 128;
    const int mTilesND  = (NCur + 127) / 128;    // 391
    const int rowsPadND = mTilesND * 128;
    const int nTiles    = (F + 127) / 128;       // 3

    {
        int total = NCur * F;
        k_init<<<(total + 255) / 256, 256>>>(g1, NCur, F);
    }
    k_flag<<<(E + 255) / 256, 256>>>(cur_idx, E);

    // --- PQ = [lastF|lastC] @ W1 + b1 via HMMA ---
    {
        size_t total = (size_t)rowsPadPQ * KPAD;
        k_convA_pq<<<(int)((total + 255) / 256), 256>>>(last_features, last_coors, NLast, F, rowsPadPQ);
    }
    k_convW<<<(NPADW * KPAD + 255) / 256, 256>>>(W1, F + 3, F);
    {
        dim3 g(mTilesPQ, nTiles);
        k_hmma<<<g, HM_NT, SMEM_HMMA_BYTES>>>(b1, NLast, F, 0);
    }

    // --- R = curC @ W1c ---
    k_r<<<2048, 256>>>(current_coors, W1, NCur, F);

    // --- edge gather/sub/relu/scatter-max + BN1 stats ---
    k_edge2<<<148 * 8, ETHREADS>>>(cur_idx, last_idx, g1, E, F);
    k_stats<<<(F + 255) / 256, 256>>>(g1, be1, 1.0f / (float)E, F, 0);

    // --- node GEMM: BN1(agg) @ W2 + b2 -> relu -> stats via HMMA ---
    {
        size_t total = (size_t)rowsPadND * KPAD;
        k_convA_node<<<(int)((total + 255) / 256), 256>>>(NCur, F, rowsPadND);
    }
    k_convW<<<(NPADW * KPAD + 255) / 256, 256>>>(W2, F, F);
    {
        dim3 g(mTilesND, nTiles);
        k_hmma<<<g, HM_NT, SMEM_HMMA_BYTES>>>(b2, NCur, F, 1);
    }
    k_stats<<<(F + 255) / 256, 256>>>(g2, be2, 1.0f / (float)NCur, F, 1);

    k_apply<<<(NCur * F + 255) / 256, 256>>>(out, NCur, F);
}